// round 13
// baseline (speedup 1.0000x reference)
#include <cuda_runtime.h>
#include <cstdint>

#define C 19
#define CP 10          // class pairs (last padded)
#define DF 256
#define NPIX_MAX 262144

// ---------------- scratch (device globals; no runtime allocation) ----------------
__device__ float g_sums[C * DF];
__device__ float g_denom[C];
__device__ int g_src_count;
__device__ uint2 g_desc_src[NPIX_MAX];   // {row<<5 | cls, bits(w=1)}
__device__ uint2 g_desc_tgt[NPIX_MAX];   // {row<<5 | cls, bits(1-conf)}
__device__ double g_total;
__device__ double g_ws;

typedef unsigned long long ull;

union F4U { float4 f; ulonglong2 u; };

__device__ __forceinline__ void fma2(ull& d, ull a, ull b) {
    asm("fma.rn.f32x2 %0, %1, %2, %0;" : "+l"(d) : "l"(a), "l"(b));
}
__device__ __forceinline__ ull dup2(float v) {
    ull r; asm("mov.b64 %0, {%1, %1};" : "=l"(r) : "f"(v)); return r;
}
__device__ __forceinline__ void unpack2(ull v, float& lo, float& hi) {
    asm("mov.b64 {%0, %1}, %2;" : "=f"(lo), "=f"(hi) : "l"(v));
}

// ---------------- K0: zero scratch (must run every replay) ----------------
__global__ void k0_zero() {
    int t = threadIdx.x;
    for (int i = t; i < C * DF; i += 256) g_sums[i] = 0.f;
    if (t < C) g_denom[t] = 0.f;
    if (t == 0) { g_total = 0.0; g_ws = 0.0; g_src_count = 0; }
}

// ---------------- K1a: denoms + ws + entry descriptors ----------------
#define K1A_BLOCKS 512
__global__ void __launch_bounds__(256) k1a_meta(
    const float* __restrict__ conf, const int* __restrict__ sarg,
    const int* __restrict__ targ, const int* __restrict__ smask, int N)
{
    __shared__ float sden[C];
    __shared__ float swsum[8];
    const int t = threadIdx.x;
    if (t < C) sden[t] = 0.f;
    float wsl = 0.f;
    __syncthreads();

    const int stride = gridDim.x * blockDim.x;
    const int iters = (N + stride - 1) / stride;
    for (int it = 0; it < iters; it++) {
        int i = it * stride + blockIdx.x * blockDim.x + t;
        int flag = 0, cs = 0;
        if (i < N) {
            flag = (smask[i] != 0);
            cs = sarg[i];
            int ct = targ[i];
            float w = 1.f - conf[i];
            if (flag) { atomicAdd(&sden[cs], 1.f); wsl += 1.f; }
            atomicAdd(&sden[ct], w);
            g_desc_tgt[i] = make_uint2(((unsigned)i << 5) | (unsigned)ct, __float_as_uint(w));
        }
        unsigned bal = __ballot_sync(0xffffffffu, flag);
        int cnt = __popc(bal);
        int bbase = 0;
        if ((t & 31) == 0 && cnt) bbase = atomicAdd(&g_src_count, cnt);
        bbase = __shfl_sync(0xffffffffu, bbase, 0);
        if (flag) {
            int rank = __popc(bal & ((1u << (t & 31)) - 1u));
            g_desc_src[bbase + rank] = make_uint2(((unsigned)i << 5) | (unsigned)cs, __float_as_uint(1.f));
        }
    }

    __syncthreads();
    if (t < C) atomicAdd(&g_denom[t], sden[t]);
    #pragma unroll
    for (int o = 16; o; o >>= 1) wsl += __shfl_down_sync(0xffffffffu, wsl, o);
    if ((t & 31) == 0) swsum[t >> 5] = wsl;
    __syncthreads();
    if (t == 0) {
        float s = 0.f;
        #pragma unroll
        for (int w = 0; w < 8; w++) s += swsum[w];
        atomicAdd(&g_ws, (double)s);
    }
}

// ---------------- K1b: streaming per-class feature sums ----
#define K1B_BLOCKS 740
__global__ void __launch_bounds__(256) k1b_sums(
    const float* __restrict__ sfeat, const float* __restrict__ tfeat, int N)
{
    __shared__ float acc[2][C * DF];   // one copy per 128-thread subgroup
    const int t = threadIdx.x;
    const int sub = t >> 7;            // 0 or 1
    const int l = t & 127;             // dim pair owner: dims [2l, 2l+1]

    for (int i = t; i < 2 * C * DF; i += 256) ((float*)acc)[i] = 0.f;
    __syncthreads();

    const int M = g_src_count;
    const int E = M + N;
    const int sg = blockIdx.x * 2 + sub;
    const int nsg = gridDim.x * 2;

    for (int base = sg * 8; base < E; base += nsg * 8) {
        float2 v[8]; float w[8]; int cls[8];
        #pragma unroll
        for (int u = 0; u < 8; u++) {
            int e = base + u;
            uint2 d; const float2* p;
            if (e < M) {
                d = __ldg(&g_desc_src[e]);
                p = (const float2*)(sfeat + (size_t)(d.x >> 5) * DF);
            } else if (e < E) {
                d = __ldg(&g_desc_tgt[e - M]);
                p = (const float2*)(tfeat + (size_t)(e - M) * DF);
            } else {
                d = make_uint2(0u, 0u);
                p = (const float2*)tfeat;
            }
            cls[u] = (int)(d.x & 31u);
            w[u] = __uint_as_float(d.y);
            v[u] = __ldg(p + l);
        }
        #pragma unroll
        for (int u = 0; u < 8; u++) {
            float2* a = (float2*)&acc[sub][cls[u] * DF + 2 * l];
            float2 av = *a;
            av.x = fmaf(w[u], v[u].x, av.x);
            av.y = fmaf(w[u], v[u].y, av.y);
            *a = av;
        }
    }

    __syncthreads();
    for (int i = t; i < C * DF; i += 256)
        atomicAdd(&g_sums[i], acc[0][i] + acc[1][i]);
}

// ---------------- K3: GEMM + entropy; class-packed, conflict-free scT ------
// Lane (g=lane>>3, sub=lane&7) handles dims (2m, 2m+1), m = j*8+sub, j=0..15.
// scT[p*128+m] = float4( c2p[2m], c2p+1[2m], c2p[2m+1], c2p+1[2m+1] ):
// subs stride 16B -> conflict-free LDS.128; halves are natural class pairs.
#define K3_THREADS 192
#define K3_GRID 296
#define K3_PER 96          // 6 warps * 16 entries

__device__ __forceinline__ const float2* k3_row_ptr2(
    int e, int M, int E, const float* sfeat, const float* tfeat)
{
    if (e < M) {
        uint2 d = __ldg(&g_desc_src[e]);
        return (const float2*)(sfeat + (size_t)(d.x >> 5) * DF);
    }
    if (e < E) return (const float2*)(tfeat + (size_t)(e - M) * DF);
    return (const float2*)tfeat;
}

__global__ void __launch_bounds__(K3_THREADS, 2) k3_entropy(
    const float* __restrict__ sfeat, const float* __restrict__ tfeat, int N)
{
    __shared__ __align__(16) float4 scT[CP * 128];
    __shared__ float bsum[K3_THREADS / 32];
    const int t = threadIdx.x;

    // build class-pair transposed centroids (zero for unseen / padded classes)
    for (int i = t; i < CP * 128; i += K3_THREADS) {
        int p = i >> 7, m = i & 127;
        int c0 = 2 * p, c1 = 2 * p + 1;
        float den0 = __ldg(&g_denom[c0]);
        float inv0 = (den0 > 0.f) ? 1.f / fmaxf(den0, 1e-12f) : 0.f;
        float a0 = g_sums[c0 * DF + 2 * m]     * inv0;
        float a1 = g_sums[c0 * DF + 2 * m + 1] * inv0;
        float b0 = 0.f, b1 = 0.f;
        if (c1 < C) {
            float den1 = __ldg(&g_denom[c1]);
            float inv1 = (den1 > 0.f) ? 1.f / fmaxf(den1, 1e-12f) : 0.f;
            b0 = g_sums[c1 * DF + 2 * m]     * inv1;
            b1 = g_sums[c1 * DF + 2 * m + 1] * inv1;
        }
        scT[i] = make_float4(a0, b0, a1, b1);
    }
    unsigned seen = 0;
    #pragma unroll
    for (int c = 0; c < C; c++) if (__ldg(&g_denom[c]) > 0.f) seen |= (1u << c);
    const int M = g_src_count;
    const int E = M + N;
    __syncthreads();

    const int warp = t >> 5, lane = t & 31;
    const int g = lane >> 3, sub = lane & 7;   // 8-lane groups
    const int eoff = warp * 16 + g * 4;        // 4 entries per group
    const int step = gridDim.x * K3_PER;
    float partial = 0.f;

    for (int base = blockIdx.x * K3_PER; base < E; base += step) {
        const int e0 = base + eoff;

        const float2* rp[4];
        #pragma unroll
        for (int i = 0; i < 4; i++) rp[i] = k3_row_ptr2(e0 + i, M, E, sfeat, tfeat);

        ull acc[4][CP];
        #pragma unroll
        for (int i = 0; i < 4; i++)
            #pragma unroll
            for (int p = 0; p < CP; p++) acc[i][p] = 0ull;

        // double-buffered row float2s (dims 2m, 2m+1), m = j*8+sub
        float2 cur[4], nxt[4];
        #pragma unroll
        for (int i = 0; i < 4; i++) cur[i] = __ldg(rp[i] + sub);

        #pragma unroll
        for (int j = 0; j < 16; j++) {
            if (j < 15) {
                #pragma unroll
                for (int i = 0; i < 4; i++) nxt[i] = __ldg(rp[i] + (j + 1) * 8 + sub);
            }
            // duplicate the 2 row dims per entry (8 dup2 per j)
            ull dr0[4], dr1[4];
            #pragma unroll
            for (int i = 0; i < 4; i++) { dr0[i] = dup2(cur[i].x); dr1[i] = dup2(cur[i].y); }

            const float4* sp = scT + j * 8 + sub;
            #pragma unroll
            for (int p = 0; p < CP; p++) {
                F4U s; s.f = sp[p * 128];    // (c2p[2m],c2p+1[2m], c2p[2m+1],c2p+1[2m+1])
                #pragma unroll
                for (int i = 0; i < 4; i++) {
                    fma2(acc[i][p], dr0[i], s.u.x);
                    fma2(acc[i][p], dr1[i], s.u.y);
                }
            }
            #pragma unroll
            for (int i = 0; i < 4; i++) cur[i] = nxt[i];
        }

        // reduce across sub lanes + entropy, per entry
        #pragma unroll
        for (int i = 0; i < 4; i++) {
            float z[2 * CP];
            #pragma unroll
            for (int p = 0; p < CP; p++) {
                float a, b; unpack2(acc[i][p], a, b);
                a += __shfl_xor_sync(0xffffffffu, a, 1);
                a += __shfl_xor_sync(0xffffffffu, a, 2);
                a += __shfl_xor_sync(0xffffffffu, a, 4);
                b += __shfl_xor_sync(0xffffffffu, b, 1);
                b += __shfl_xor_sync(0xffffffffu, b, 2);
                b += __shfl_xor_sync(0xffffffffu, b, 4);
                z[2 * p] = a; z[2 * p + 1] = b;
            }
            int e = e0 + i;
            float w;
            if (e < M) w = 1.f;
            else if (e < E) w = __uint_as_float(__ldg(&g_desc_tgt[e - M]).y);
            else w = 0.f;

            float m = -3.4e38f;
            #pragma unroll
            for (int c = 0; c < C; c++) if ((seen >> c) & 1u) m = fmaxf(m, z[c]);
            float S = 0.f, U = 0.f;
            #pragma unroll
            for (int c = 0; c < C; c++) if ((seen >> c) & 1u) {
                float ex = __expf(z[c] - m);
                S += ex;
                U = fmaf(z[c], ex, U);
            }
            float ent = U / S - m - __logf(S);   // = sum_c p*logp over seen classes
            if (sub == 0) partial += w * ent;
        }
    }

    #pragma unroll
    for (int o = 16; o; o >>= 1) partial += __shfl_down_sync(0xffffffffu, partial, o);
    if (lane == 0) bsum[warp] = partial;
    __syncthreads();
    if (t == 0) {
        float s = 0.f;
        #pragma unroll
        for (int wp = 0; wp < K3_THREADS / 32; wp++) s += bsum[wp];
        atomicAdd(&g_total, (double)s);
    }
}

// ---------------- K2: write centroid block of the output ----------------
__global__ void k2_centroids(float* __restrict__ out) {
    int c = blockIdx.x, d = threadIdx.x;
    float den = g_denom[c];
    bool seen = den > 0.f;
    float s = g_sums[c * DF + d];
    out[c * DF + d] = seen ? s / fmaxf(den, 1e-12f) : __int_as_float(0x7f800000);
}

// ---------------- K4: finalize loss ----------------
__global__ void k4_final(float* __restrict__ out, int N) {
    out[C * DF] = (float)(-(g_total / (g_ws + (double)N)));
}

// ---------------- launch ----------------
extern "C" void kernel_launch(void* const* d_in, const int* in_sizes, int n_in,
                              void* d_out, int out_size) {
    const float* sfeat = (const float*)d_in[0];
    const float* tfeat = (const float*)d_in[1];
    const float* conf  = (const float*)d_in[2];
    const int*   sarg  = (const int*)d_in[3];
    const int*   targ  = (const int*)d_in[4];
    const int*   smask = (const int*)d_in[5];
    float* out = (float*)d_out;
    int N = in_sizes[2];   // target_conf element count = N_PIX

    k0_zero<<<1, 256>>>();
    k1a_meta<<<K1A_BLOCKS, 256>>>(conf, sarg, targ, smask, N);
    k1b_sums<<<K1B_BLOCKS, 256>>>(sfeat, tfeat, N);
    k3_entropy<<<K3_GRID, K3_THREADS>>>(sfeat, tfeat, N);   // capture index 3
    k2_centroids<<<C, DF>>>(out);
    k4_final<<<1, 1>>>(out, N);
}

// round 17
// speedup vs baseline: 1.0015x; 1.0015x over previous
#include <cuda_runtime.h>
#include <cstdint>

#define C 19
#define CP 10          // class pairs (last padded)
#define DF 256
#define NPIX_MAX 262144

// ---------------- scratch (device globals; no runtime allocation) ----------------
__device__ float g_sums[C * DF];
__device__ float g_denom[C];
__device__ int g_src_count;
__device__ uint2 g_desc_src[NPIX_MAX];   // {row<<5 | cls, bits(w=1)}
__device__ uint2 g_desc_tgt[NPIX_MAX];   // {row<<5 | cls, bits(1-conf)}
__device__ double g_total;
__device__ double g_ws;

typedef unsigned long long ull;

union F4U { float4 f; ulonglong2 u; };

__device__ __forceinline__ void fma2(ull& d, ull a, ull b) {
    asm("fma.rn.f32x2 %0, %1, %2, %0;" : "+l"(d) : "l"(a), "l"(b));
}
__device__ __forceinline__ ull dup2(float v) {
    ull r; asm("mov.b64 %0, {%1, %1};" : "=l"(r) : "f"(v)); return r;
}
__device__ __forceinline__ void unpack2(ull v, float& lo, float& hi) {
    asm("mov.b64 {%0, %1}, %2;" : "=f"(lo), "=f"(hi) : "l"(v));
}

// ---------------- K0: zero scratch (must run every replay) ----------------
__global__ void k0_zero() {
    int t = threadIdx.x;
    for (int i = t; i < C * DF; i += 256) g_sums[i] = 0.f;
    if (t < C) g_denom[t] = 0.f;
    if (t == 0) { g_total = 0.0; g_ws = 0.0; g_src_count = 0; }
}

// ---------------- K1a: denoms + ws + entry descriptors ----------------
#define K1A_BLOCKS 512
__global__ void __launch_bounds__(256) k1a_meta(
    const float* __restrict__ conf, const int* __restrict__ sarg,
    const int* __restrict__ targ, const int* __restrict__ smask, int N)
{
    __shared__ float sden[C];
    __shared__ float swsum[8];
    const int t = threadIdx.x;
    if (t < C) sden[t] = 0.f;
    float wsl = 0.f;
    __syncthreads();

    const int stride = gridDim.x * blockDim.x;
    const int iters = (N + stride - 1) / stride;
    for (int it = 0; it < iters; it++) {
        int i = it * stride + blockIdx.x * blockDim.x + t;
        int flag = 0, cs = 0;
        if (i < N) {
            flag = (smask[i] != 0);
            cs = sarg[i];
            int ct = targ[i];
            float w = 1.f - conf[i];
            if (flag) { atomicAdd(&sden[cs], 1.f); wsl += 1.f; }
            atomicAdd(&sden[ct], w);
            g_desc_tgt[i] = make_uint2(((unsigned)i << 5) | (unsigned)ct, __float_as_uint(w));
        }
        unsigned bal = __ballot_sync(0xffffffffu, flag);
        int cnt = __popc(bal);
        int bbase = 0;
        if ((t & 31) == 0 && cnt) bbase = atomicAdd(&g_src_count, cnt);
        bbase = __shfl_sync(0xffffffffu, bbase, 0);
        if (flag) {
            int rank = __popc(bal & ((1u << (t & 31)) - 1u));
            g_desc_src[bbase + rank] = make_uint2(((unsigned)i << 5) | (unsigned)cs, __float_as_uint(1.f));
        }
    }

    __syncthreads();
    if (t < C) atomicAdd(&g_denom[t], sden[t]);
    #pragma unroll
    for (int o = 16; o; o >>= 1) wsl += __shfl_down_sync(0xffffffffu, wsl, o);
    if ((t & 31) == 0) swsum[t >> 5] = wsl;
    __syncthreads();
    if (t == 0) {
        float s = 0.f;
        #pragma unroll
        for (int w = 0; w < 8; w++) s += swsum[w];
        atomicAdd(&g_ws, (double)s);
    }
}

// ---------------- K1b: streaming per-class feature sums ----
#define K1B_BLOCKS 740
__global__ void __launch_bounds__(256) k1b_sums(
    const float* __restrict__ sfeat, const float* __restrict__ tfeat, int N)
{
    __shared__ float acc[2][C * DF];   // one copy per 128-thread subgroup
    const int t = threadIdx.x;
    const int sub = t >> 7;            // 0 or 1
    const int l = t & 127;             // dim pair owner: dims [2l, 2l+1]

    for (int i = t; i < 2 * C * DF; i += 256) ((float*)acc)[i] = 0.f;
    __syncthreads();

    const int M = g_src_count;
    const int E = M + N;
    const int sg = blockIdx.x * 2 + sub;
    const int nsg = gridDim.x * 2;

    for (int base = sg * 8; base < E; base += nsg * 8) {
        float2 v[8]; float w[8]; int cls[8];
        #pragma unroll
        for (int u = 0; u < 8; u++) {
            int e = base + u;
            uint2 d; const float2* p;
            if (e < M) {
                d = __ldg(&g_desc_src[e]);
                p = (const float2*)(sfeat + (size_t)(d.x >> 5) * DF);
            } else if (e < E) {
                d = __ldg(&g_desc_tgt[e - M]);
                p = (const float2*)(tfeat + (size_t)(e - M) * DF);
            } else {
                d = make_uint2(0u, 0u);
                p = (const float2*)tfeat;
            }
            cls[u] = (int)(d.x & 31u);
            w[u] = __uint_as_float(d.y);
            v[u] = __ldg(p + l);
        }
        #pragma unroll
        for (int u = 0; u < 8; u++) {
            float2* a = (float2*)&acc[sub][cls[u] * DF + 2 * l];
            float2 av = *a;
            av.x = fmaf(w[u], v[u].x, av.x);
            av.y = fmaf(w[u], v[u].y, av.y);
            *a = av;
        }
    }

    __syncthreads();
    for (int i = t; i < C * DF; i += 256)
        atomicAdd(&g_sums[i], acc[0][i] + acc[1][i]);
}

// ---------------- K3: GEMM + entropy; class-packed, conflict-free scT ------
// Lane (g=lane>>3, sub=lane&7) handles dims (2m, 2m+1), m = j*8+sub, j=0..15.
// scT[p*128+m] = float4( c2p[2m], c2p+1[2m], c2p[2m+1], c2p+1[2m+1] ):
// subs stride 16B -> conflict-free LDS.128; halves are natural class pairs.
#define K3_THREADS 192
#define K3_GRID 296
#define K3_PER 96          // 6 warps * 16 entries

__device__ __forceinline__ const float2* k3_row_ptr2(
    int e, int M, int E, const float* sfeat, const float* tfeat)
{
    if (e < M) {
        uint2 d = __ldg(&g_desc_src[e]);
        return (const float2*)(sfeat + (size_t)(d.x >> 5) * DF);
    }
    if (e < E) return (const float2*)(tfeat + (size_t)(e - M) * DF);
    return (const float2*)tfeat;
}

__global__ void __launch_bounds__(K3_THREADS, 2) k3_entropy(
    const float* __restrict__ sfeat, const float* __restrict__ tfeat, int N)
{
    __shared__ __align__(16) float4 scT[CP * 128];
    __shared__ float bsum[K3_THREADS / 32];
    const int t = threadIdx.x;

    // build class-pair transposed centroids (zero for unseen / padded classes)
    for (int i = t; i < CP * 128; i += K3_THREADS) {
        int p = i >> 7, m = i & 127;
        int c0 = 2 * p, c1 = 2 * p + 1;
        float den0 = __ldg(&g_denom[c0]);
        float inv0 = (den0 > 0.f) ? 1.f / fmaxf(den0, 1e-12f) : 0.f;
        float a0 = g_sums[c0 * DF + 2 * m]     * inv0;
        float a1 = g_sums[c0 * DF + 2 * m + 1] * inv0;
        float b0 = 0.f, b1 = 0.f;
        if (c1 < C) {
            float den1 = __ldg(&g_denom[c1]);
            float inv1 = (den1 > 0.f) ? 1.f / fmaxf(den1, 1e-12f) : 0.f;
            b0 = g_sums[c1 * DF + 2 * m]     * inv1;
            b1 = g_sums[c1 * DF + 2 * m + 1] * inv1;
        }
        scT[i] = make_float4(a0, b0, a1, b1);
    }
    unsigned seen = 0;
    #pragma unroll
    for (int c = 0; c < C; c++) if (__ldg(&g_denom[c]) > 0.f) seen |= (1u << c);
    const int M = g_src_count;
    const int E = M + N;
    __syncthreads();

    const int warp = t >> 5, lane = t & 31;
    const int g = lane >> 3, sub = lane & 7;   // 8-lane groups
    const int eoff = warp * 16 + g * 4;        // 4 entries per group
    const int step = gridDim.x * K3_PER;
    float partial = 0.f;

    for (int base = blockIdx.x * K3_PER; base < E; base += step) {
        const int e0 = base + eoff;

        const float2* rp[4];
        #pragma unroll
        for (int i = 0; i < 4; i++) rp[i] = k3_row_ptr2(e0 + i, M, E, sfeat, tfeat);

        ull acc[4][CP];
        #pragma unroll
        for (int i = 0; i < 4; i++)
            #pragma unroll
            for (int p = 0; p < CP; p++) acc[i][p] = 0ull;

        // double-buffered row float2s (dims 2m, 2m+1), m = j*8+sub
        float2 cur[4], nxt[4];
        #pragma unroll
        for (int i = 0; i < 4; i++) cur[i] = __ldg(rp[i] + sub);

        #pragma unroll
        for (int j = 0; j < 16; j++) {
            if (j < 15) {
                #pragma unroll
                for (int i = 0; i < 4; i++) nxt[i] = __ldg(rp[i] + (j + 1) * 8 + sub);
            }
            // duplicate the 2 row dims per entry (8 dup2 per j)
            ull dr0[4], dr1[4];
            #pragma unroll
            for (int i = 0; i < 4; i++) { dr0[i] = dup2(cur[i].x); dr1[i] = dup2(cur[i].y); }

            const float4* sp = scT + j * 8 + sub;
            #pragma unroll
            for (int p = 0; p < CP; p++) {
                F4U s; s.f = sp[p * 128];    // (c2p[2m],c2p+1[2m], c2p[2m+1],c2p+1[2m+1])
                #pragma unroll
                for (int i = 0; i < 4; i++) {
                    fma2(acc[i][p], dr0[i], s.u.x);
                    fma2(acc[i][p], dr1[i], s.u.y);
                }
            }
            #pragma unroll
            for (int i = 0; i < 4; i++) cur[i] = nxt[i];
        }

        // reduce across sub lanes + entropy, per entry
        #pragma unroll
        for (int i = 0; i < 4; i++) {
            float z[2 * CP];
            #pragma unroll
            for (int p = 0; p < CP; p++) {
                float a, b; unpack2(acc[i][p], a, b);
                a += __shfl_xor_sync(0xffffffffu, a, 1);
                a += __shfl_xor_sync(0xffffffffu, a, 2);
                a += __shfl_xor_sync(0xffffffffu, a, 4);
                b += __shfl_xor_sync(0xffffffffu, b, 1);
                b += __shfl_xor_sync(0xffffffffu, b, 2);
                b += __shfl_xor_sync(0xffffffffu, b, 4);
                z[2 * p] = a; z[2 * p + 1] = b;
            }
            int e = e0 + i;
            float w;
            if (e < M) w = 1.f;
            else if (e < E) w = __uint_as_float(__ldg(&g_desc_tgt[e - M]).y);
            else w = 0.f;

            float m = -3.4e38f;
            #pragma unroll
            for (int c = 0; c < C; c++) if ((seen >> c) & 1u) m = fmaxf(m, z[c]);
            float S = 0.f, U = 0.f;
            #pragma unroll
            for (int c = 0; c < C; c++) if ((seen >> c) & 1u) {
                float ex = __expf(z[c] - m);
                S += ex;
                U = fmaf(z[c], ex, U);
            }
            float ent = U / S - m - __logf(S);   // = sum_c p*logp over seen classes
            if (sub == 0) partial += w * ent;
        }
    }

    #pragma unroll
    for (int o = 16; o; o >>= 1) partial += __shfl_down_sync(0xffffffffu, partial, o);
    if (lane == 0) bsum[warp] = partial;
    __syncthreads();
    if (t == 0) {
        float s = 0.f;
        #pragma unroll
        for (int wp = 0; wp < K3_THREADS / 32; wp++) s += bsum[wp];
        atomicAdd(&g_total, (double)s);
    }
}

// ---------------- K2: write centroid block of the output ----------------
__global__ void k2_centroids(float* __restrict__ out) {
    int c = blockIdx.x, d = threadIdx.x;
    float den = g_denom[c];
    bool seen = den > 0.f;
    float s = g_sums[c * DF + d];
    out[c * DF + d] = seen ? s / fmaxf(den, 1e-12f) : __int_as_float(0x7f800000);
}

// ---------------- K4: finalize loss ----------------
__global__ void k4_final(float* __restrict__ out, int N) {
    out[C * DF] = (float)(-(g_total / (g_ws + (double)N)));
}

// ---------------- launch ----------------
extern "C" void kernel_launch(void* const* d_in, const int* in_sizes, int n_in,
                              void* d_out, int out_size) {
    const float* sfeat = (const float*)d_in[0];
    const float* tfeat = (const float*)d_in[1];
    const float* conf  = (const float*)d_in[2];
    const int*   sarg  = (const int*)d_in[3];
    const int*   targ  = (const int*)d_in[4];
    const int*   smask = (const int*)d_in[5];
    float* out = (float*)d_out;
    int N = in_sizes[2];   // target_conf element count = N_PIX

    k0_zero<<<1, 256>>>();
    k1a_meta<<<K1A_BLOCKS, 256>>>(conf, sarg, targ, smask, N);
    k1b_sums<<<K1B_BLOCKS, 256>>>(sfeat, tfeat, N);
    k3_entropy<<<K3_GRID, K3_THREADS>>>(sfeat, tfeat, N);   // capture index 3
    k2_centroids<<<C, DF>>>(out);
    k4_final<<<1, 1>>>(out, N);
}